// round 6
// baseline (speedup 1.0000x reference)
#include <cuda_runtime.h>

#define Bn   8
#define Cn   19
#define Hn   256
#define Wn   256
#define HWn  (Hn * Wn)
#define NPIX (Bn * HWn)
#define FINF 1e6f

// Scratch (no allocations allowed): ~4 MB total.
__device__ __align__(16) float g_g2[NPIX];   // squared row-distance per pixel
__device__ __align__(16) float g_w[NPIX];    // boundary weight per pixel
__device__ int   g_rowb[Bn * Hn];            // per-row "has boundary" flag
__device__ float g_part[512];                // per-block partial sums (kC grid)
__device__ int   g_ctr = 0;                  // last-block-done counter (self-resetting)

// ---------------------------------------------------------------------------
// Kernel A: block = one (image, row). Separable 3x3 min/max -> boundary flag,
// then exact 1D row distance via a 256-bit ballot bitmask + clz/ffs search.
// ---------------------------------------------------------------------------
__global__ __launch_bounds__(256) void kA(const int* __restrict__ tgt) {
    const int bh = blockIdx.x;
    const int b  = bh >> 8;
    const int h  = bh & 255;
    const int j  = threadIdx.x;

    const int* img = tgt + b * HWn;
    const int rm = (h > 0      ? h - 1 : 0     ) * Wn;
    const int r0 = h * Wn;
    const int rp = (h < Hn - 1 ? h + 1 : Hn - 1) * Wn;

    const int v0 = img[rm + j];
    const int v1 = img[r0 + j];
    const int v2 = img[rp + j];

    __shared__ int cmn[Wn], cmx[Wn];
    cmn[j] = min(v0, min(v1, v2));
    cmx[j] = max(v0, max(v1, v2));
    __syncthreads();

    const int jm = (j > 0      ? j - 1 : 0     );
    const int jp = (j < Wn - 1 ? j + 1 : Wn - 1);
    const int mn = min(cmn[jm], min(cmn[j], cmn[jp]));
    const int mx = max(cmx[jm], max(cmx[j], cmx[jp]));
    const int isb = (mx != mn);

    const unsigned wm = __ballot_sync(0xffffffffu, isb);
    __shared__ unsigned smask[8];
    if ((j & 31) == 0) smask[j >> 5] = wm;
    __syncthreads();

    unsigned m[8];
    #pragma unroll
    for (int w = 0; w < 8; ++w) m[w] = smask[w];

    const int wj = j >> 5, bj = j & 31;
    int dl = 1 << 30;
    unsigned cur = m[wj] & ((2u << bj) - 1u);
    if (cur) {
        dl = bj - (31 - __clz(cur));
    } else {
        #pragma unroll
        for (int w = 6; w >= 0; --w)
            if (w < wj && dl > (1 << 29) && m[w])
                dl = j - (w * 32 + 31 - __clz(m[w]));
    }
    int dr = 1 << 30;
    cur = m[wj] & ~((1u << bj) - 1u);
    if (cur) {
        dr = (__ffs(cur) - 1) - bj;
    } else {
        #pragma unroll
        for (int w = 1; w < 8; ++w)
            if (w > wj && dr > (1 << 29) && m[w])
                dr = w * 32 + (__ffs(m[w]) - 1) - j;
    }
    const int d = min(dl, dr);
    const float g = (d > Wn) ? FINF : (float)d;
    g_g2[bh * Wn + j] = g * g;

    if (j == 0)
        g_rowb[bh] = (m[0] | m[1] | m[2] | m[3] | m[4] | m[5] | m[6] | m[7]) != 0;
}

// ---------------------------------------------------------------------------
// Kernel B: block = one (image, row). Pruned exact column EDT + boundary
// weight, writes g_w. g_g2 is L2-resident (2 MB); loads are coalesced 128B
// row segments.
// ---------------------------------------------------------------------------
__global__ __launch_bounds__(256) void kB() {
    const int bh = blockIdx.x;
    const int b  = bh >> 8;
    const int i  = bh & 255;
    const int j  = threadIdx.x;

    // image-level has-boundary: OR of the 256 per-row flags
    const int hasb = __syncthreads_or(g_rowb[(b << 8) | j]);

    const float* g2c = g_g2 + b * HWn + j;
    float best = g2c[i * Wn];
    #pragma unroll 1
    for (int r = 1; r < Hn; ++r) {
        const float rr = (float)(r * r);
        if (rr >= best) break;              // exact: g2 >= 0
        const int ku = i - r, kd = i + r;
        if (ku >= 0) best = fminf(best, rr + g2c[ku * Wn]);
        if (kd < Hn) best = fminf(best, rr + g2c[kd * Wn]);
    }
    g_w[bh * Wn + j] = hasb ? __expf(-0.2f * sqrtf(best)) : 1.0f;
}

// ---------------------------------------------------------------------------
// Kernel C: pure streaming CE. 512 blocks x 256 threads, 4 px/thread.
// Channel loads explicitly batched in chunks of 5/5/5/4 float4 loads to keep
// real MLP high; no irregular control flow between batches.
// ---------------------------------------------------------------------------
__global__ __launch_bounds__(256) void kC(const float* __restrict__ x,
                                          const int*   __restrict__ tgt,
                                          float* __restrict__ out) {
    const int tid = threadIdx.x;
    const int b   = blockIdx.x >> 6;                       // image
    const int p0  = (((blockIdx.x & 63) << 8) | tid) << 2; // pixel*4 in image

    const int4   t4 = *(const int4*)(tgt + b * HWn + p0);
    const float4 w4 = *(const float4*)(g_w + b * HWn + p0);
    const float* xb = x + (size_t)b * Cn * HWn + p0;

    float4 s  = make_float4(0.f, 0.f, 0.f, 0.f);
    float4 xt = make_float4(0.f, 0.f, 0.f, 0.f);

    #pragma unroll
    for (int ch = 0; ch < 4; ++ch) {              // chunks: 5,5,5,4 channels
        const int cbase = ch * 5;
        const int clen  = (ch == 3) ? 4 : 5;
        float4 vv[5];
        #pragma unroll
        for (int c = 0; c < 5; ++c)
            if (c < clen)
                vv[c] = *(const float4*)(xb + (size_t)(cbase + c) * HWn);
        #pragma unroll
        for (int c = 0; c < 5; ++c) {
            if (c < clen) {
                const float4 v = vv[c];
                s.x += __expf(v.x); s.y += __expf(v.y);
                s.z += __expf(v.z); s.w += __expf(v.w);
                const int cc = cbase + c;
                if (cc == t4.x) xt.x = v.x;
                if (cc == t4.y) xt.y = v.y;
                if (cc == t4.z) xt.z = v.z;
                if (cc == t4.w) xt.w = v.w;
            }
        }
    }

    float acc = (__logf(s.x) - xt.x) * w4.x
              + (__logf(s.y) - xt.y) * w4.y
              + (__logf(s.z) - xt.z) * w4.z
              + (__logf(s.w) - xt.w) * w4.w;

    // ---- deterministic block reduction ----
    #pragma unroll
    for (int o = 16; o > 0; o >>= 1)
        acc += __shfl_down_sync(0xffffffffu, acc, o);
    __shared__ float red[8];
    if ((tid & 31) == 0) red[tid >> 5] = acc;
    __syncthreads();
    if (tid == 0) {
        float v = 0.f;
        #pragma unroll
        for (int k = 0; k < 8; ++k) v += red[k];
        g_part[blockIdx.x] = v;
    }

    // ---- last-block-done final reduction (deterministic order) ----
    __shared__ int isLast;
    if (tid == 0) {
        __threadfence();
        isLast = (atomicAdd(&g_ctr, 1) == gridDim.x - 1);
    }
    __syncthreads();
    if (isLast) {
        double ds = (double)g_part[tid] + (double)g_part[tid + 256];
        #pragma unroll
        for (int o = 16; o > 0; o >>= 1)
            ds += __shfl_down_sync(0xffffffffu, ds, o);
        __shared__ double dred[8];
        if ((tid & 31) == 0) dred[tid >> 5] = ds;
        __syncthreads();
        if (tid == 0) {
            double v = 0.0;
            #pragma unroll
            for (int k = 0; k < 8; ++k) v += dred[k];
            out[0] = (float)(v / (double)NPIX);
            g_ctr = 0;  // reset for next graph replay
        }
    }
}

// ---------------------------------------------------------------------------
extern "C" void kernel_launch(void* const* d_in, const int* in_sizes, int n_in,
                              void* d_out, int out_size) {
    const float* x;
    const int*   tgt;
    if (in_sizes[0] == Bn * Cn * HWn) {
        x   = (const float*)d_in[0];
        tgt = (const int*)d_in[1];
    } else {
        x   = (const float*)d_in[1];
        tgt = (const int*)d_in[0];
    }

    kA<<<Bn * Hn, 256>>>(tgt);
    kB<<<Bn * Hn, 256>>>();
    kC<<<512, 256>>>(x, tgt, (float*)d_out);
}

// round 8
// speedup vs baseline: 1.1404x; 1.1404x over previous
#include <cuda_runtime.h>

#define Bn   8
#define Cn   19
#define Hn   256
#define Wn   256
#define HWn  (Hn * Wn)
#define NPIX (Bn * HWn)
#define FINF 1e6f

// Scratch (no allocations allowed).
__device__ __align__(16) float g_g2[NPIX];   // squared row-distance per pixel
__device__ int   g_rowb[Bn * Hn];            // per-row "has boundary" flag
__device__ float g_part[512];                // per-block partial sums (kC grid)
__device__ int   g_ctr = 0;                  // last-block-done counter (self-resetting)

// ---------------------------------------------------------------------------
// Kernel A: block = (image, 4 rows), 256 threads, 4 cols/thread (int4).
// Separable 3x3 min/max -> boundary nibble -> 256-bit row mask (shuffle-OR
// packing), then only TWO clz/ffs searches per thread; the remaining 6
// distances follow from exact recurrences dl(j+1)=isb?0:dl(j)+1 (and mirror).
// ---------------------------------------------------------------------------
__global__ __launch_bounds__(256) void kA(const int* __restrict__ tgt) {
    const int blk  = blockIdx.x;        // 0..511
    const int b    = blk >> 6;
    const int rg   = blk & 63;          // 4-row group
    const int t    = threadIdx.x;
    const int rloc = t >> 6;            // 0..3
    const int row  = rg * 4 + rloc;
    const int q    = t & 63;            // col-quad index
    const int c4   = q << 2;

    const int* img = tgt + b * HWn;
    const int rm = (row > 0      ? row - 1 : 0     ) * Wn;
    const int r0 = row * Wn;
    const int rp = (row < Hn - 1 ? row + 1 : Hn - 1) * Wn;

    const int4 a = *(const int4*)(img + rm + c4);
    const int4 c = *(const int4*)(img + r0 + c4);
    const int4 e = *(const int4*)(img + rp + c4);

    int4 vmn, vmx;
    vmn.x = min(a.x, min(c.x, e.x));  vmx.x = max(a.x, max(c.x, e.x));
    vmn.y = min(a.y, min(c.y, e.y));  vmx.y = max(a.y, max(c.y, e.y));
    vmn.z = min(a.z, min(c.z, e.z));  vmx.z = max(a.z, max(c.z, e.z));
    vmn.w = min(a.w, min(c.w, e.w));  vmx.w = max(a.w, max(c.w, e.w));

    __shared__ int4 smn[4][64], smx[4][64];
    smn[rloc][q] = vmn;
    smx[rloc][q] = vmx;
    __syncthreads();

    const int lmn = (q > 0)  ? smn[rloc][q - 1].w : vmn.x;
    const int lmx = (q > 0)  ? smx[rloc][q - 1].w : vmx.x;
    const int rmn = (q < 63) ? smn[rloc][q + 1].x : vmn.w;
    const int rmx = (q < 63) ? smx[rloc][q + 1].x : vmx.w;

    const int i0 = max(lmx,   max(vmx.x, vmx.y)) != min(lmn,   min(vmn.x, vmn.y));
    const int i1 = max(vmx.x, max(vmx.y, vmx.z)) != min(vmn.x, min(vmn.y, vmn.z));
    const int i2 = max(vmx.y, max(vmx.z, vmx.w)) != min(vmn.y, min(vmn.z, vmn.w));
    const int i3 = max(vmx.z, max(vmx.w, rmx  )) != min(vmn.z, min(vmn.w, rmn  ));

    // pack nibbles into 32-bit mask words (8 lanes -> 1 word)
    const unsigned lane = t & 31;
    const unsigned nib  = (unsigned)(i0 | (i1 << 1) | (i2 << 2) | (i3 << 3));
    unsigned wrd = nib << ((lane & 7) * 4);
    wrd |= __shfl_xor_sync(0xffffffffu, wrd, 1);
    wrd |= __shfl_xor_sync(0xffffffffu, wrd, 2);
    wrd |= __shfl_xor_sync(0xffffffffu, wrd, 4);

    __shared__ unsigned smask[4][8];
    if ((lane & 7) == 0) {
        const int half = (t >> 5) & 1;              // which 128-col half of the row
        smask[rloc][half * 4 + (lane >> 3)] = wrd;
    }
    __syncthreads();

    unsigned m[8];
    #pragma unroll
    for (int k = 0; k < 8; ++k) m[k] = smask[rloc][k];

    // nearest set bit <= c4  (includes c4 itself)
    const int wj = c4 >> 5, bj = c4 & 31;
    int dl = 1 << 30;
    unsigned cur = m[wj] & ((2u << bj) - 1u);
    if (cur) {
        dl = bj - (31 - __clz(cur));
    } else {
        #pragma unroll
        for (int w = 6; w >= 0; --w)
            if (w < wj && dl > (1 << 29) && m[w])
                dl = c4 - (w * 32 + 31 - __clz(m[w]));
    }
    // nearest set bit >= c4+3  (includes c4+3 itself)
    const int j3 = c4 + 3;
    const int wj3 = j3 >> 5, bj3 = j3 & 31;
    int dr = 1 << 30;
    cur = m[wj3] & ~((1u << bj3) - 1u);
    if (cur) {
        dr = (__ffs(cur) - 1) - bj3;
    } else {
        #pragma unroll
        for (int w = 1; w < 8; ++w)
            if (w > wj3 && dr > (1 << 29) && m[w])
                dr = w * 32 + (__ffs(m[w]) - 1) - j3;
    }

    // exact recurrences for interior columns
    const int dl0 = dl;
    const int dl1 = i1 ? 0 : dl0 + 1;
    const int dl2 = i2 ? 0 : dl1 + 1;
    const int dl3 = i3 ? 0 : dl2 + 1;
    const int dr3 = dr;
    const int dr2 = i2 ? 0 : dr3 + 1;
    const int dr1 = i1 ? 0 : dr2 + 1;
    const int dr0 = i0 ? 0 : dr1 + 1;

    const int d0 = min(dl0, dr0);
    const int d1 = min(dl1, dr1);
    const int d2 = min(dl2, dr2);
    const int d3 = min(dl3, dr3);
    const float g0 = (d0 > Wn) ? FINF : (float)d0;
    const float g1 = (d1 > Wn) ? FINF : (float)d1;
    const float g2v = (d2 > Wn) ? FINF : (float)d2;
    const float g3 = (d3 > Wn) ? FINF : (float)d3;

    *(float4*)(g_g2 + b * HWn + row * Wn + c4) =
        make_float4(g0 * g0, g1 * g1, g2v * g2v, g3 * g3);

    if (q == 0)
        g_rowb[(b << 8) | row] =
            (m[0] | m[1] | m[2] | m[3] | m[4] | m[5] | m[6] | m[7]) != 0;
}

// ---------------------------------------------------------------------------
// Kernel C: fused. 512 blocks x 256 threads, 4 px/thread.
// Chunked float4 single-pass CE (streaming DRAM traffic up-front), then
// pruned exact column EDT (L2-resident g2) + boundary weight, combine,
// deterministic block + last-block final reduction.
// ---------------------------------------------------------------------------
__global__ __launch_bounds__(256) void kC(const float* __restrict__ x,
                                          const int*   __restrict__ tgt,
                                          float* __restrict__ out) {
    const int tid = threadIdx.x;
    const int b   = blockIdx.x >> 6;                       // image
    const int p0  = (((blockIdx.x & 63) << 8) | tid) << 2; // pixel*4 in image
    const int row = p0 >> 8;
    const int c0  = p0 & 255;

    // image-level has-boundary (OR of 256 per-row flags)
    const int hasb = __syncthreads_or(g_rowb[(b << 8) | tid]);

    // ---- one-pass CE over 19 channels, chunked float4 loads ----
    const int4   t4 = *(const int4*)(tgt + b * HWn + p0);
    const float* xb = x + (size_t)b * Cn * HWn + p0;

    float4 s  = make_float4(0.f, 0.f, 0.f, 0.f);
    float4 xt = make_float4(0.f, 0.f, 0.f, 0.f);

    #pragma unroll
    for (int ch = 0; ch < 4; ++ch) {              // chunks: 5,5,5,4 channels
        const int cbase = ch * 5;
        const int clen  = (ch == 3) ? 4 : 5;
        float4 vv[5];
        #pragma unroll
        for (int c = 0; c < 5; ++c)
            if (c < clen)
                vv[c] = *(const float4*)(xb + (size_t)(cbase + c) * HWn);
        #pragma unroll
        for (int c = 0; c < 5; ++c) {
            if (c < clen) {
                const float4 v = vv[c];
                s.x += __expf(v.x); s.y += __expf(v.y);
                s.z += __expf(v.z); s.w += __expf(v.w);
                const int cc = cbase + c;
                if (cc == t4.x) xt.x = v.x;
                if (cc == t4.y) xt.y = v.y;
                if (cc == t4.z) xt.z = v.z;
                if (cc == t4.w) xt.w = v.w;
            }
        }
    }

    // ---- pruned exact column EDT on 4 adjacent columns ----
    const float* gp = g_g2 + b * HWn + c0;
    float4 best = *(const float4*)(gp + row * Wn);
    #pragma unroll 1
    for (int r = 1; r < Hn; ++r) {
        const float rr = (float)(r * r);
        const float bm = fmaxf(fmaxf(best.x, best.y), fmaxf(best.z, best.w));
        if (rr >= bm) break;                      // exact: g2 >= 0
        const int ku = row - r, kd = row + r;
        if (ku >= 0) {
            const float4 g = *(const float4*)(gp + ku * Wn);
            best.x = fminf(best.x, rr + g.x); best.y = fminf(best.y, rr + g.y);
            best.z = fminf(best.z, rr + g.z); best.w = fminf(best.w, rr + g.w);
        }
        if (kd < Hn) {
            const float4 g = *(const float4*)(gp + kd * Wn);
            best.x = fminf(best.x, rr + g.x); best.y = fminf(best.y, rr + g.y);
            best.z = fminf(best.z, rr + g.z); best.w = fminf(best.w, rr + g.w);
        }
    }
    float4 w;
    if (hasb) {
        w.x = __expf(-0.2f * sqrtf(best.x));
        w.y = __expf(-0.2f * sqrtf(best.y));
        w.z = __expf(-0.2f * sqrtf(best.z));
        w.w = __expf(-0.2f * sqrtf(best.w));
    } else {
        w.x = w.y = w.z = w.w = 1.0f;
    }

    float acc = (__logf(s.x) - xt.x) * w.x
              + (__logf(s.y) - xt.y) * w.y
              + (__logf(s.z) - xt.z) * w.z
              + (__logf(s.w) - xt.w) * w.w;

    // ---- deterministic block reduction ----
    #pragma unroll
    for (int o = 16; o > 0; o >>= 1)
        acc += __shfl_down_sync(0xffffffffu, acc, o);
    __shared__ float red[8];
    if ((tid & 31) == 0) red[tid >> 5] = acc;
    __syncthreads();
    if (tid == 0) {
        float v = 0.f;
        #pragma unroll
        for (int k = 0; k < 8; ++k) v += red[k];
        g_part[blockIdx.x] = v;
    }

    // ---- last-block-done final reduction (deterministic order) ----
    __shared__ int isLast;
    if (tid == 0) {
        __threadfence();
        isLast = (atomicAdd(&g_ctr, 1) == gridDim.x - 1);
    }
    __syncthreads();
    if (isLast) {
        double ds = (double)g_part[tid] + (double)g_part[tid + 256];
        #pragma unroll
        for (int o = 16; o > 0; o >>= 1)
            ds += __shfl_down_sync(0xffffffffu, ds, o);
        __shared__ double dred[8];
        if ((tid & 31) == 0) dred[tid >> 5] = ds;
        __syncthreads();
        if (tid == 0) {
            double v = 0.0;
            #pragma unroll
            for (int k = 0; k < 8; ++k) v += dred[k];
            out[0] = (float)(v / (double)NPIX);
            g_ctr = 0;  // reset for next graph replay
        }
    }
}

// ---------------------------------------------------------------------------
extern "C" void kernel_launch(void* const* d_in, const int* in_sizes, int n_in,
                              void* d_out, int out_size) {
    const float* x;
    const int*   tgt;
    if (in_sizes[0] == Bn * Cn * HWn) {
        x   = (const float*)d_in[0];
        tgt = (const int*)d_in[1];
    } else {
        x   = (const float*)d_in[1];
        tgt = (const int*)d_in[0];
    }

    kA<<<512, 256>>>(tgt);
    kC<<<512, 256>>>(x, tgt, (float*)d_out);
}